// round 1
// baseline (speedup 1.0000x reference)
#include <cuda_runtime.h>
#include <math.h>

// Problem dims
#define NTOK 16384          // B*S = 16*1024
#define DQK  192            // 3*F = feature dim of q/k/v
#define SEQ  1024

// ---------------- device scratch (allocation-free) ----------------
__device__ float  g_q[NTOK * DQK];
__device__ float  g_k[NTOK * DQK];
__device__ float  g_v[NTOK * DQK];
__device__ float2 g_U[48][16][16];   // [qkv*16+split][row][col]

// ---------------- complex gate helpers (register state) ----------------
// wire w -> bit (8 >> w) in the flat 16-dim state index.

__device__ __forceinline__ void gate_rx(float2* v, int w, float ch, float sh) {
    int bit = 8 >> w;
#pragma unroll
    for (int n = 0; n < 16; n++) if (!(n & bit)) {
        float2 a = v[n], b = v[n | bit];
        // [ch, -i sh; -i sh, ch]
        v[n]       = make_float2(ch * a.x + sh * b.y, ch * a.y - sh * b.x);
        v[n | bit] = make_float2(ch * b.x + sh * a.y, ch * b.y - sh * a.x);
    }
}

__device__ __forceinline__ void gate_ry(float2* v, int w, float ch, float sh) {
    int bit = 8 >> w;
#pragma unroll
    for (int n = 0; n < 16; n++) if (!(n & bit)) {
        float2 a = v[n], b = v[n | bit];
        v[n]       = make_float2(ch * a.x - sh * b.x, ch * a.y - sh * b.y);
        v[n | bit] = make_float2(sh * a.x + ch * b.x, sh * a.y + ch * b.y);
    }
}

__device__ __forceinline__ void gate_rz(float2* v, int w, float ch, float sh) {
    int bit = 8 >> w;
#pragma unroll
    for (int n = 0; n < 16; n++) {
        float2 a = v[n];
        if (n & bit) v[n] = make_float2(ch * a.x - sh * a.y, ch * a.y + sh * a.x);  // * e^{+i t/2}
        else         v[n] = make_float2(ch * a.x + sh * a.y, ch * a.y - sh * a.x);  // * e^{-i t/2}
    }
}

__device__ __forceinline__ void gate_h(float2* v, int w) {
    int bit = 8 >> w;
    const float r = 0.70710678118654752440f;
#pragma unroll
    for (int n = 0; n < 16; n++) if (!(n & bit)) {
        float2 a = v[n], b = v[n | bit];
        v[n]       = make_float2(r * (a.x + b.x), r * (a.y + b.y));
        v[n | bit] = make_float2(r * (a.x - b.x), r * (a.y - b.y));
    }
}

__device__ __forceinline__ void gate_crx(float2* v, int c, int g, float ch, float sh) {
    int bc = 8 >> c, bg = 8 >> g;
#pragma unroll
    for (int n = 0; n < 16; n++) if ((n & bc) && !(n & bg)) {
        float2 a = v[n], b = v[n | bg];
        v[n]      = make_float2(ch * a.x + sh * b.y, ch * a.y - sh * b.x);
        v[n | bg] = make_float2(ch * b.x + sh * a.y, ch * b.y - sh * a.x);
    }
}

__device__ __forceinline__ void gate_cphase(float2* v, int j, int i, float phi) {
    int bj = 8 >> j, bi = 8 >> i;
    float sp, cp;
    sincosf(phi, &sp, &cp);
#pragma unroll
    for (int n = 0; n < 16; n++) if ((n & bj) && (n & bi)) {
        float2 a = v[n];
        v[n] = make_float2(cp * a.x - sp * a.y, cp * a.y + sp * a.x);
    }
}

__device__ __forceinline__ void gate_iswap(float2* v, int w0, int w1) {
    int b0 = 8 >> w0, b1 = 8 >> w1;
#pragma unroll
    for (int n = 0; n < 16; n++) if (!(n & b0) && (n & b1)) {
        int m = (n | b0) & ~b1;       // partner state (b0=1, b1=0)
        float2 a = v[n], b = v[m];
        v[n] = make_float2(-b.y, b.x);   // i * b
        v[m] = make_float2(-a.y, a.x);   // i * a
    }
}

__device__ __forceinline__ void gate_swap(float2* v, int w0, int w1) {
    int b0 = 8 >> w0, b1 = 8 >> w1;
#pragma unroll
    for (int n = 0; n < 16; n++) if (!(n & b0) && (n & b1)) {
        int m = (n | b0) & ~b1;
        float2 t = v[n]; v[n] = v[m]; v[m] = t;
    }
}

// ---------------- Kernel A: build the 48 fixed 16x16 unitaries ----------------
__global__ void __launch_bounds__(16) build_U_kernel(const float* __restrict__ W,
                                                     const float* __restrict__ EW,
                                                     const float* __restrict__ TW) {
    const int u   = blockIdx.x;    // 0..47  (qkv*16 + split)
    const int col = threadIdx.x;   // 0..15
    const float* w  = W  + u * 12;   // [L][i], L in 0..2, i in 0..3
    const float* ew = EW + u * 12;
    const float* tw = TW + u * 12;

    float2 v[16];
#pragma unroll
    for (int n = 0; n < 16; n++) v[n] = make_float2(n == col ? 1.f : 0.f, 0.f);

    const float PI = 3.14159265358979323846f;

#pragma unroll
    for (int L = 0; L < 3; L++) {
        // per-qubit RX, RY, RZ with the same angle
#pragma unroll
        for (int i = 0; i < 4; i++) {
            float sh, ch;
            sincosf(0.5f * w[L * 4 + i], &sh, &ch);
            gate_rx(v, i, ch, sh);
            gate_ry(v, i, ch, sh);
            gate_rz(v, i, ch, sh);
        }
        // advanced dynamic entanglement
#pragma unroll
        for (int i = 0; i < 4; i++) {
            float sh, ch;
            sincosf(0.5f * ew[L * 4 + i], &sh, &ch);
            gate_crx(v, i, (i + 2) & 3, ch, sh);
            gate_crx(v, i, (i + 3) & 3, ch, sh);
        }
        gate_iswap(v, 0, 1); gate_iswap(v, 1, 2); gate_iswap(v, 2, 3); gate_iswap(v, 3, 0);
        // Toffoli(0,1 -> 2): swap amplitudes of |110*> and |111*>
        { float2 t = v[12]; v[12] = v[14]; v[14] = t;
          t = v[13]; v[13] = v[15]; v[15] = t; }
        // quantum tunneling
#pragma unroll
        for (int i = 0; i < 3; i++) {
            float sh, ch;
            sincosf(0.5f * tw[L * 4 + i], &sh, &ch);
            gate_crx(v, i, i + 1, ch, sh);
        }
        { float sh, ch; sincosf(0.5f * tw[L * 4 + 3], &sh, &ch); gate_crx(v, 3, 0, ch, sh); }
        // QPE
#pragma unroll
        for (int i = 0; i < 4; i++) gate_h(v, i);
#pragma unroll
        for (int i = 1; i < 4; i++)
#pragma unroll
            for (int j = 0; j < i; j++)
                gate_cphase(v, j, i, PI / (float)(1 << (i - j)));
        gate_swap(v, 0, 3); gate_swap(v, 1, 2);
#pragma unroll
        for (int i = 0; i < 4; i++) {
            gate_h(v, i);
#pragma unroll
            for (int j = 0; j < i; j++)
                gate_cphase(v, j, i, -PI / (float)(1 << (i - j)));
        }
    }

#pragma unroll
    for (int n = 0; n < 16; n++) g_U[u][n][col] = v[n];
}

// ---------------- Kernel B: per-token QKV via 16x16 complex matvec ----------------
__global__ void __launch_bounds__(128) qkv_kernel(const float* __restrict__ x) {
    const int sp = blockIdx.x;                              // split 0..15
    const int t  = blockIdx.y * 128 + threadIdx.x;          // token 0..16383
    const int tid = threadIdx.x;

    __shared__ float2 sU[3][16][16];
    for (int r = tid; r < 3 * 256; r += 128) {
        int q = r >> 8, rem = r & 255;
        sU[q][rem >> 4][rem & 15] = g_U[q * 16 + sp][rem >> 4][rem & 15];
    }
    __syncthreads();

    // embedding: x[b,s, sp*4 .. sp*4+3]
    const float4 xv = reinterpret_cast<const float4*>(x)[t * 16 + sp];
    float cs[4], sn[4];
    sincosf(0.5f * xv.x, &sn[0], &cs[0]);
    sincosf(0.5f * xv.y, &sn[1], &cs[1]);
    sincosf(0.5f * xv.z, &sn[2], &cs[2]);
    sincosf(0.5f * xv.w, &sn[3], &cs[3]);

    float2 e[16];
#pragma unroll
    for (int n = 0; n < 16; n++) {
        float m = (n & 8 ? sn[0] : cs[0]) * (n & 4 ? sn[1] : cs[1]) *
                  (n & 2 ? sn[2] : cs[2]) * (n & 1 ? sn[3] : cs[3]);
        int pc = __popc(n) & 3;   // (-i)^pc
        e[n] = (pc == 0) ? make_float2(m, 0.f) :
               (pc == 1) ? make_float2(0.f, -m) :
               (pc == 2) ? make_float2(-m, 0.f) : make_float2(0.f, m);
    }

#pragma unroll
    for (int q = 0; q < 3; q++) {
        float2 psi[16];
#pragma unroll
        for (int r = 0; r < 16; r++) {
            float ar = 0.f, ai = 0.f;
#pragma unroll
            for (int k = 0; k < 16; k++) {
                float2 Uv = sU[q][r][k];
                ar = fmaf(Uv.x, e[k].x, ar); ar = fmaf(-Uv.y, e[k].y, ar);
                ai = fmaf(Uv.x, e[k].y, ai); ai = fmaf( Uv.y, e[k].x, ai);
            }
            psi[r] = make_float2(ar, ai);
        }
        float o[12];
#pragma unroll
        for (int w = 0; w < 4; w++) {
            int bit = 8 >> w;
            float z = 0.f, xr = 0.f, yi = 0.f;
#pragma unroll
            for (int n = 0; n < 16; n++) {
                if (n & bit) continue;
                float2 a = psi[n], b = psi[n | bit];
                z  += (a.x * a.x + a.y * a.y) - (b.x * b.x + b.y * b.y);
                xr += a.x * b.x + a.y * b.y;
                yi += a.x * b.y - a.y * b.x;
            }
            o[w] = z; o[4 + w] = 2.f * xr; o[8 + w] = 2.f * yi;
        }
        float* dst = (q == 0 ? g_q : (q == 1 ? g_k : g_v)) + (size_t)t * DQK + sp * 12;
#pragma unroll
        for (int m = 0; m < 12; m++) dst[m] = o[m];
    }
}

// ---------------- Kernel C1: scores = Q K^T / 2   (per batch 1024x1024x192) ----------------
__global__ void __launch_bounds__(256) scores_kernel(float* __restrict__ S) {
    const int b  = blockIdx.z;
    const int m0 = blockIdx.y * 128, n0 = blockIdx.x * 128;
    const float* Q = g_q + (size_t)b * SEQ * DQK;
    const float* K = g_k + (size_t)b * SEQ * DQK;

    __shared__ float sA[16][132];
    __shared__ float sB[16][132];

    const int tid = threadIdx.x;
    const int tm = (tid >> 4) << 3, tn = (tid & 15) << 3;

    float acc[8][8];
#pragma unroll
    for (int i = 0; i < 8; i++)
#pragma unroll
        for (int j = 0; j < 8; j++) acc[i][j] = 0.f;

    for (int k0 = 0; k0 < DQK; k0 += 16) {
#pragma unroll
        for (int r = 0; r < 8; r++) {
            int idx = r * 256 + tid;
            int kk = idx & 15, mm = idx >> 4;
            sA[kk][mm] = Q[(size_t)(m0 + mm) * DQK + k0 + kk];
            sB[kk][mm] = K[(size_t)(n0 + mm) * DQK + k0 + kk];
        }
        __syncthreads();
#pragma unroll
        for (int kk = 0; kk < 16; kk++) {
            float a[8], bb[8];
#pragma unroll
            for (int i = 0; i < 8; i++) a[i]  = sA[kk][tm + i];
#pragma unroll
            for (int j = 0; j < 8; j++) bb[j] = sB[kk][tn + j];
#pragma unroll
            for (int i = 0; i < 8; i++)
#pragma unroll
                for (int j = 0; j < 8; j++) acc[i][j] = fmaf(a[i], bb[j], acc[i][j]);
        }
        __syncthreads();
    }

    float* Sp = S + ((size_t)b << 20);
#pragma unroll
    for (int i = 0; i < 8; i++) {
        float4 w0 = make_float4(0.5f * acc[i][0], 0.5f * acc[i][1], 0.5f * acc[i][2], 0.5f * acc[i][3]);
        float4 w1 = make_float4(0.5f * acc[i][4], 0.5f * acc[i][5], 0.5f * acc[i][6], 0.5f * acc[i][7]);
        float* row = Sp + (size_t)(m0 + tm + i) * SEQ + n0 + tn;
        *reinterpret_cast<float4*>(row)     = w0;
        *reinterpret_cast<float4*>(row + 4) = w1;
    }
}

// ---------------- Kernel C2: in-place row softmax over 1024 ----------------
__global__ void __launch_bounds__(256) softmax_kernel(float* __restrict__ A) {
    const int row = blockIdx.x;
    float* p = A + (size_t)row * SEQ;
    const int t = threadIdx.x;

    float4 v = *reinterpret_cast<float4*>(p + t * 4);
    float mx = fmaxf(fmaxf(v.x, v.y), fmaxf(v.z, v.w));
#pragma unroll
    for (int o = 16; o; o >>= 1) mx = fmaxf(mx, __shfl_xor_sync(0xffffffffu, mx, o));

    __shared__ float red[8];
    __shared__ float bmax, bsum;
    if ((t & 31) == 0) red[t >> 5] = mx;
    __syncthreads();
    if (t < 8) {
        float m = red[t];
#pragma unroll
        for (int o = 4; o; o >>= 1) m = fmaxf(m, __shfl_xor_sync(0xffu, m, o));
        if (t == 0) bmax = m;
    }
    __syncthreads();
    const float M = bmax;

    float e0 = expf(v.x - M), e1 = expf(v.y - M), e2 = expf(v.z - M), e3 = expf(v.w - M);
    float s = e0 + e1 + e2 + e3;
#pragma unroll
    for (int o = 16; o; o >>= 1) s += __shfl_xor_sync(0xffffffffu, s, o);
    if ((t & 31) == 0) red[t >> 5] = s;
    __syncthreads();
    if (t < 8) {
        float m = red[t];
#pragma unroll
        for (int o = 4; o; o >>= 1) m += __shfl_xor_sync(0xffu, m, o);
        if (t == 0) bsum = m;
    }
    __syncthreads();
    const float inv = 1.f / bsum;
    *reinterpret_cast<float4*>(p + t * 4) = make_float4(e0 * inv, e1 * inv, e2 * inv, e3 * inv);
}

// ---------------- Kernel C3: O = A @ V   (per batch 1024x192x1024) ----------------
__global__ void __launch_bounds__(256) o_kernel(const float* __restrict__ A, float* __restrict__ O) {
    const int b  = blockIdx.z;
    const int n0 = blockIdx.x * 64, m0 = blockIdx.y * 128;
    const float* Ab = A + ((size_t)b << 20);
    const float* V  = g_v + (size_t)b * SEQ * DQK;

    __shared__ float sA[16][132];
    __shared__ float sB[16][68];

    const int tid = threadIdx.x;
    const int tm = (tid >> 4) << 3, tn = (tid & 15) << 2;

    float acc[8][4];
#pragma unroll
    for (int i = 0; i < 8; i++)
#pragma unroll
        for (int j = 0; j < 4; j++) acc[i][j] = 0.f;

    for (int k0 = 0; k0 < SEQ; k0 += 16) {
#pragma unroll
        for (int r = 0; r < 8; r++) {
            int idx = r * 256 + tid;
            int kk = idx & 15, mm = idx >> 4;
            sA[kk][mm] = Ab[(size_t)(m0 + mm) * SEQ + k0 + kk];
        }
#pragma unroll
        for (int r = 0; r < 4; r++) {
            int idx = r * 256 + tid;
            int nn = idx & 63, kk = idx >> 6;
            sB[kk][nn] = V[(size_t)(k0 + kk) * DQK + n0 + nn];
        }
        __syncthreads();
#pragma unroll
        for (int kk = 0; kk < 16; kk++) {
            float a[8], bb[4];
#pragma unroll
            for (int i = 0; i < 8; i++) a[i]  = sA[kk][tm + i];
#pragma unroll
            for (int j = 0; j < 4; j++) bb[j] = sB[kk][tn + j];
#pragma unroll
            for (int i = 0; i < 8; i++)
#pragma unroll
                for (int j = 0; j < 4; j++) acc[i][j] = fmaf(a[i], bb[j], acc[i][j]);
        }
        __syncthreads();
    }

#pragma unroll
    for (int i = 0; i < 8; i++) {
        float4 w = make_float4(acc[i][0], acc[i][1], acc[i][2], acc[i][3]);
        *reinterpret_cast<float4*>(O + (size_t)b * SEQ * DQK + (size_t)(m0 + tm + i) * DQK + n0 + tn) = w;
    }
}

// ---------------- Kernel C4: in-place LayerNorm over 192 with gamma/beta ----------------
__global__ void __launch_bounds__(192) ln_kernel(float* __restrict__ O,
                                                 const float* __restrict__ gamma,
                                                 const float* __restrict__ beta) {
    const int row = blockIdx.x;
    const int t = threadIdx.x;
    float* p = O + (size_t)row * DQK;
    float v = p[t];
    float s = v, s2 = v * v;
#pragma unroll
    for (int o = 16; o; o >>= 1) {
        s  += __shfl_xor_sync(0xffffffffu, s, o);
        s2 += __shfl_xor_sync(0xffffffffu, s2, o);
    }
    __shared__ float ws[6], ws2[6];
    __shared__ float mb[2];
    if ((t & 31) == 0) { ws[t >> 5] = s; ws2[t >> 5] = s2; }
    __syncthreads();
    if (t == 0) {
        float a = 0.f, b2 = 0.f;
#pragma unroll
        for (int i = 0; i < 6; i++) { a += ws[i]; b2 += ws2[i]; }
        float mean = a * (1.f / 192.f);
        float var  = b2 * (1.f / 192.f) - mean * mean;
        mb[0] = mean;
        mb[1] = rsqrtf(var + 1e-5f);
    }
    __syncthreads();
    p[t] = (v - mb[0]) * mb[1] * gamma[t] + beta[t];
}

// ---------------- launch ----------------
extern "C" void kernel_launch(void* const* d_in, const int* in_sizes, int n_in,
                              void* d_out, int out_size) {
    const float* x     = (const float*)d_in[0];
    const float* w     = (const float*)d_in[1];
    const float* ew    = (const float*)d_in[2];
    const float* tw    = (const float*)d_in[3];
    const float* gamma = (const float*)d_in[4];
    const float* beta  = (const float*)d_in[5];
    (void)in_sizes; (void)n_in; (void)out_size;

    float* out      = (float*)d_out;
    float* out_o    = out;                                  // [16,1024,192]
    float* out_attn = out + (size_t)NTOK * DQK;             // [16,1024,1024]

    build_U_kernel<<<48, 16>>>(w, ew, tw);
    qkv_kernel<<<dim3(16, NTOK / 128), 128>>>(x);
    scores_kernel<<<dim3(8, 8, 16), 256>>>(out_attn);
    softmax_kernel<<<NTOK, 256>>>(out_attn);
    o_kernel<<<dim3(3, 8, 16), 256>>>(out_attn, out_o);
    ln_kernel<<<NTOK, 192>>>(out_o, gamma, beta);
}

// round 2
// speedup vs baseline: 1.5594x; 1.5594x over previous
#include <cuda_runtime.h>
#include <math.h>

// Problem dims
#define NTOK 16384          // B*S = 16*1024
#define DQK  192            // 3*F
#define SEQ  1024

// ---------------- device scratch (allocation-free) ----------------
__device__ float  g_q[NTOK * DQK];
__device__ float  g_k[NTOK * DQK];
__device__ float  g_v[NTOK * DQK];
__device__ float2 g_U[48][16][16];   // [qkv*16+split][row][col]

// ---------------- f32x2 packed helpers ----------------
__device__ __forceinline__ unsigned long long pack2(float lo, float hi) {
    unsigned long long r;
    asm("mov.b64 %0, {%1,%2};" : "=l"(r) : "f"(lo), "f"(hi));
    return r;
}
__device__ __forceinline__ void ffma2(unsigned long long& d, unsigned long long a, unsigned long long b) {
    asm("fma.rn.f32x2 %0, %1, %2, %0;" : "+l"(d) : "l"(a), "l"(b));
}
__device__ __forceinline__ float2 unpack2(unsigned long long v) {
    float2 r;
    asm("mov.b64 {%0,%1}, %2;" : "=f"(r.x), "=f"(r.y) : "l"(v));
    return r;
}

// ---------------- complex gate helpers (register state) ----------------
__device__ __forceinline__ void gate_rx(float2* v, int w, float ch, float sh) {
    int bit = 8 >> w;
#pragma unroll
    for (int n = 0; n < 16; n++) if (!(n & bit)) {
        float2 a = v[n], b = v[n | bit];
        v[n]       = make_float2(ch * a.x + sh * b.y, ch * a.y - sh * b.x);
        v[n | bit] = make_float2(ch * b.x + sh * a.y, ch * b.y - sh * a.x);
    }
}
__device__ __forceinline__ void gate_ry(float2* v, int w, float ch, float sh) {
    int bit = 8 >> w;
#pragma unroll
    for (int n = 0; n < 16; n++) if (!(n & bit)) {
        float2 a = v[n], b = v[n | bit];
        v[n]       = make_float2(ch * a.x - sh * b.x, ch * a.y - sh * b.y);
        v[n | bit] = make_float2(sh * a.x + ch * b.x, sh * a.y + ch * b.y);
    }
}
__device__ __forceinline__ void gate_rz(float2* v, int w, float ch, float sh) {
    int bit = 8 >> w;
#pragma unroll
    for (int n = 0; n < 16; n++) {
        float2 a = v[n];
        if (n & bit) v[n] = make_float2(ch * a.x - sh * a.y, ch * a.y + sh * a.x);
        else         v[n] = make_float2(ch * a.x + sh * a.y, ch * a.y - sh * a.x);
    }
}
__device__ __forceinline__ void gate_h(float2* v, int w) {
    int bit = 8 >> w;
    const float r = 0.70710678118654752440f;
#pragma unroll
    for (int n = 0; n < 16; n++) if (!(n & bit)) {
        float2 a = v[n], b = v[n | bit];
        v[n]       = make_float2(r * (a.x + b.x), r * (a.y + b.y));
        v[n | bit] = make_float2(r * (a.x - b.x), r * (a.y - b.y));
    }
}
__device__ __forceinline__ void gate_crx(float2* v, int c, int g, float ch, float sh) {
    int bc = 8 >> c, bg = 8 >> g;
#pragma unroll
    for (int n = 0; n < 16; n++) if ((n & bc) && !(n & bg)) {
        float2 a = v[n], b = v[n | bg];
        v[n]      = make_float2(ch * a.x + sh * b.y, ch * a.y - sh * b.x);
        v[n | bg] = make_float2(ch * b.x + sh * a.y, ch * b.y - sh * a.x);
    }
}
__device__ __forceinline__ void gate_cphase(float2* v, int j, int i, float phi) {
    int bj = 8 >> j, bi = 8 >> i;
    float sp, cp;
    sincosf(phi, &sp, &cp);
#pragma unroll
    for (int n = 0; n < 16; n++) if ((n & bj) && (n & bi)) {
        float2 a = v[n];
        v[n] = make_float2(cp * a.x - sp * a.y, cp * a.y + sp * a.x);
    }
}
__device__ __forceinline__ void gate_iswap(float2* v, int w0, int w1) {
    int b0 = 8 >> w0, b1 = 8 >> w1;
#pragma unroll
    for (int n = 0; n < 16; n++) if (!(n & b0) && (n & b1)) {
        int m = (n | b0) & ~b1;
        float2 a = v[n], b = v[m];
        v[n] = make_float2(-b.y, b.x);
        v[m] = make_float2(-a.y, a.x);
    }
}
__device__ __forceinline__ void gate_swap(float2* v, int w0, int w1) {
    int b0 = 8 >> w0, b1 = 8 >> w1;
#pragma unroll
    for (int n = 0; n < 16; n++) if (!(n & b0) && (n & b1)) {
        int m = (n | b0) & ~b1;
        float2 t = v[n]; v[n] = v[m]; v[m] = t;
    }
}

// ---------------- Kernel A: build 48 fixed 16x16 unitaries ----------------
__global__ void __launch_bounds__(16) build_U_kernel(const float* __restrict__ W,
                                                     const float* __restrict__ EW,
                                                     const float* __restrict__ TW) {
    const int u   = blockIdx.x;
    const int col = threadIdx.x;
    const float* w  = W  + u * 12;
    const float* ew = EW + u * 12;
    const float* tw = TW + u * 12;

    float2 v[16];
#pragma unroll
    for (int n = 0; n < 16; n++) v[n] = make_float2(n == col ? 1.f : 0.f, 0.f);

    const float PI = 3.14159265358979323846f;

#pragma unroll
    for (int L = 0; L < 3; L++) {
#pragma unroll
        for (int i = 0; i < 4; i++) {
            float sh, ch;
            sincosf(0.5f * w[L * 4 + i], &sh, &ch);
            gate_rx(v, i, ch, sh);
            gate_ry(v, i, ch, sh);
            gate_rz(v, i, ch, sh);
        }
#pragma unroll
        for (int i = 0; i < 4; i++) {
            float sh, ch;
            sincosf(0.5f * ew[L * 4 + i], &sh, &ch);
            gate_crx(v, i, (i + 2) & 3, ch, sh);
            gate_crx(v, i, (i + 3) & 3, ch, sh);
        }
        gate_iswap(v, 0, 1); gate_iswap(v, 1, 2); gate_iswap(v, 2, 3); gate_iswap(v, 3, 0);
        { float2 t = v[12]; v[12] = v[14]; v[14] = t;
          t = v[13]; v[13] = v[15]; v[15] = t; }
#pragma unroll
        for (int i = 0; i < 3; i++) {
            float sh, ch;
            sincosf(0.5f * tw[L * 4 + i], &sh, &ch);
            gate_crx(v, i, i + 1, ch, sh);
        }
        { float sh, ch; sincosf(0.5f * tw[L * 4 + 3], &sh, &ch); gate_crx(v, 3, 0, ch, sh); }
#pragma unroll
        for (int i = 0; i < 4; i++) gate_h(v, i);
#pragma unroll
        for (int i = 1; i < 4; i++)
#pragma unroll
            for (int j = 0; j < i; j++)
                gate_cphase(v, j, i, PI / (float)(1 << (i - j)));
        gate_swap(v, 0, 3); gate_swap(v, 1, 2);
#pragma unroll
        for (int i = 0; i < 4; i++) {
            gate_h(v, i);
#pragma unroll
            for (int j = 0; j < i; j++)
                gate_cphase(v, j, i, -PI / (float)(1 << (i - j)));
        }
    }

#pragma unroll
    for (int n = 0; n < 16; n++) g_U[u][n][col] = v[n];
}

// ---------------- Kernel B: per-token QKV via packed 16x16 complex matvec ----------------
__global__ void __launch_bounds__(128) qkv_kernel(const float* __restrict__ x) {
    const int sp  = blockIdx.x;                       // split 0..15
    const int t0  = blockIdx.y * 128;
    const int tid = threadIdx.x;
    const int t   = t0 + tid;

    __shared__ unsigned long long sUp[3][16][16];   // (Ux,Ux)
    __shared__ unsigned long long sUm[3][16][16];   // (-Uy,Uy)
    __shared__ float so[128][13];                   // staging, padded

    for (int r0 = tid; r0 < 768; r0 += 128) {
        int q = r0 >> 8, rem = r0 & 255;
        float2 Uv = g_U[q * 16 + sp][rem >> 4][rem & 15];
        sUp[q][rem >> 4][rem & 15] = pack2(Uv.x, Uv.x);
        sUm[q][rem >> 4][rem & 15] = pack2(-Uv.y, Uv.y);
    }
    __syncthreads();

    const float4 xv = reinterpret_cast<const float4*>(x)[(size_t)t * 16 + sp];
    float cs[4], sn[4];
    sincosf(0.5f * xv.x, &sn[0], &cs[0]);
    sincosf(0.5f * xv.y, &sn[1], &cs[1]);
    sincosf(0.5f * xv.z, &sn[2], &cs[2]);
    sincosf(0.5f * xv.w, &sn[3], &cs[3]);

    unsigned long long ep[16], er[16];
#pragma unroll
    for (int n = 0; n < 16; n++) {
        float m = (n & 8 ? sn[0] : cs[0]) * (n & 4 ? sn[1] : cs[1]) *
                  (n & 2 ? sn[2] : cs[2]) * (n & 1 ? sn[3] : cs[3]);
        int pc = __popc(n) & 3;   // (-i)^pc
        float ex = (pc == 0) ? m : (pc == 2) ? -m : 0.f;
        float ey = (pc == 1) ? -m : (pc == 3) ? m : 0.f;
        ep[n] = pack2(ex, ey);
        er[n] = pack2(ey, ex);
    }

#pragma unroll
    for (int q = 0; q < 3; q++) {
        float2 psi[16];
#pragma unroll
        for (int r = 0; r < 16; r++) {
            unsigned long long acc = pack2(0.f, 0.f);
#pragma unroll
            for (int k = 0; k < 16; k++) {
                ffma2(acc, sUp[q][r][k], ep[k]);
                ffma2(acc, sUm[q][r][k], er[k]);
            }
            psi[r] = unpack2(acc);
        }
        float o[12];
#pragma unroll
        for (int w = 0; w < 4; w++) {
            int bit = 8 >> w;
            float z = 0.f, xr = 0.f, yi = 0.f;
#pragma unroll
            for (int n = 0; n < 16; n++) {
                if (n & bit) continue;
                float2 a = psi[n], b = psi[n | bit];
                z  += (a.x * a.x + a.y * a.y) - (b.x * b.x + b.y * b.y);
                xr += a.x * b.x + a.y * b.y;
                yi += a.x * b.y - a.y * b.x;
            }
            o[w] = z; o[4 + w] = 2.f * xr; o[8 + w] = 2.f * yi;
        }
        __syncthreads();
#pragma unroll
        for (int m = 0; m < 12; m++) so[tid][m] = o[m];
        __syncthreads();
        float* base = (q == 0 ? g_q : (q == 1 ? g_k : g_v)) + (size_t)t0 * DQK + sp * 12;
        for (int idx = tid; idx < 1536; idx += 128) {
            int row = idx / 12, col = idx - row * 12;
            base[(size_t)row * DQK + col] = so[row][col];
        }
    }
}

// ---------------- Kernel C1: scores = Q K^T / 2 (128x128 tile, f32x2) ----------------
__global__ void __launch_bounds__(256) scores_kernel(float* __restrict__ S) {
    const int b  = blockIdx.z;
    const int m0 = blockIdx.y * 128, n0 = blockIdx.x * 128;
    const float* Q = g_q + (size_t)b * SEQ * DQK;
    const float* K = g_k + (size_t)b * SEQ * DQK;

    __shared__ __align__(16) float sA[16][128];   // [k][m]
    __shared__ __align__(16) float sB[16][128];   // [k][n]

    const int tid = threadIdx.x;
    const int row = tid & 127;
    const int kq  = tid >> 7;                 // 0..1
    const int am  = (tid >> 4) << 2;          // 0..60
    const int tn4 = (tid & 15) << 2;          // 0..60

    unsigned long long acc[8][4];
#pragma unroll
    for (int i = 0; i < 8; i++)
#pragma unroll
        for (int j = 0; j < 4; j++) acc[i][j] = pack2(0.f, 0.f);

    float4 pq0, pq1, pk0, pk1;
    const size_t qrow = (size_t)(m0 + row) * DQK;
    const size_t krow = (size_t)(n0 + row) * DQK;

#define SC_LOAD(kc) { int k0 = (kc) * 16; \
    pq0 = *reinterpret_cast<const float4*>(&Q[qrow + k0 + kq * 4]); \
    pq1 = *reinterpret_cast<const float4*>(&Q[qrow + k0 + (kq + 2) * 4]); \
    pk0 = *reinterpret_cast<const float4*>(&K[krow + k0 + kq * 4]); \
    pk1 = *reinterpret_cast<const float4*>(&K[krow + k0 + (kq + 2) * 4]); }

#define SC_STORE() { int c0 = kq * 4, c1 = (kq + 2) * 4; \
    sA[c0 + 0][row] = pq0.x; sA[c0 + 1][row] = pq0.y; sA[c0 + 2][row] = pq0.z; sA[c0 + 3][row] = pq0.w; \
    sA[c1 + 0][row] = pq1.x; sA[c1 + 1][row] = pq1.y; sA[c1 + 2][row] = pq1.z; sA[c1 + 3][row] = pq1.w; \
    sB[c0 + 0][row] = pk0.x; sB[c0 + 1][row] = pk0.y; sB[c0 + 2][row] = pk0.z; sB[c0 + 3][row] = pk0.w; \
    sB[c1 + 0][row] = pk1.x; sB[c1 + 1][row] = pk1.y; sB[c1 + 2][row] = pk1.z; sB[c1 + 3][row] = pk1.w; }

    SC_LOAD(0); SC_STORE(); __syncthreads();

    for (int kc = 0; kc < 12; kc++) {
        if (kc < 11) SC_LOAD(kc + 1);
#pragma unroll
        for (int kk = 0; kk < 16; kk++) {
            float4 a0 = *reinterpret_cast<const float4*>(&sA[kk][am]);
            float4 a1 = *reinterpret_cast<const float4*>(&sA[kk][64 + am]);
            const unsigned long long* br = reinterpret_cast<const unsigned long long*>(&sB[kk][0]);
            unsigned long long b0 = br[tn4 >> 1], b1 = br[(tn4 >> 1) + 1];
            unsigned long long b2 = br[(64 + tn4) >> 1], b3 = br[((64 + tn4) >> 1) + 1];
            float av[8] = {a0.x, a0.y, a0.z, a0.w, a1.x, a1.y, a1.z, a1.w};
#pragma unroll
            for (int i = 0; i < 8; i++) {
                unsigned long long ap = pack2(av[i], av[i]);
                ffma2(acc[i][0], ap, b0);
                ffma2(acc[i][1], ap, b1);
                ffma2(acc[i][2], ap, b2);
                ffma2(acc[i][3], ap, b3);
            }
        }
        __syncthreads();
        if (kc < 11) { SC_STORE(); __syncthreads(); }
    }

    float* Sp = S + ((size_t)b << 20);
#pragma unroll
    for (int i = 0; i < 8; i++) {
        int mi = m0 + ((i < 4) ? (am + i) : (64 + am + i - 4));
        float2 p0 = unpack2(acc[i][0]), p1 = unpack2(acc[i][1]);
        float2 p2 = unpack2(acc[i][2]), p3 = unpack2(acc[i][3]);
        float* rowp = Sp + (size_t)mi * SEQ + n0;
        *reinterpret_cast<float4*>(&rowp[tn4])      = make_float4(0.5f * p0.x, 0.5f * p0.y, 0.5f * p1.x, 0.5f * p1.y);
        *reinterpret_cast<float4*>(&rowp[64 + tn4]) = make_float4(0.5f * p2.x, 0.5f * p2.y, 0.5f * p3.x, 0.5f * p3.y);
    }
}

// ---------------- Kernel C2: in-place row softmax over 1024 ----------------
__global__ void __launch_bounds__(256) softmax_kernel(float* __restrict__ A) {
    const int row = blockIdx.x;
    float* p = A + (size_t)row * SEQ;
    const int t = threadIdx.x;

    float4 v = *reinterpret_cast<float4*>(p + t * 4);
    float mx = fmaxf(fmaxf(v.x, v.y), fmaxf(v.z, v.w));
#pragma unroll
    for (int o = 16; o; o >>= 1) mx = fmaxf(mx, __shfl_xor_sync(0xffffffffu, mx, o));

    __shared__ float red[8];
    __shared__ float bmax, bsum;
    if ((t & 31) == 0) red[t >> 5] = mx;
    __syncthreads();
    if (t < 8) {
        float m = red[t];
#pragma unroll
        for (int o = 4; o; o >>= 1) m = fmaxf(m, __shfl_xor_sync(0xffu, m, o));
        if (t == 0) bmax = m;
    }
    __syncthreads();
    const float M = bmax;

    float e0 = expf(v.x - M), e1 = expf(v.y - M), e2 = expf(v.z - M), e3 = expf(v.w - M);
    float s = e0 + e1 + e2 + e3;
#pragma unroll
    for (int o = 16; o; o >>= 1) s += __shfl_xor_sync(0xffffffffu, s, o);
    if ((t & 31) == 0) red[t >> 5] = s;
    __syncthreads();
    if (t < 8) {
        float m = red[t];
#pragma unroll
        for (int o = 4; o; o >>= 1) m += __shfl_xor_sync(0xffu, m, o);
        if (t == 0) bsum = m;
    }
    __syncthreads();
    const float inv = 1.f / bsum;
    *reinterpret_cast<float4*>(p + t * 4) = make_float4(e0 * inv, e1 * inv, e2 * inv, e3 * inv);
}

// ---------------- Kernel C3: O = A @ V (128x192 tile, full-width, f32x2) ----------------
__global__ void __launch_bounds__(256) o_kernel(const float* __restrict__ A, float* __restrict__ O) {
    const int b  = blockIdx.z;
    const int m0 = blockIdx.y * 128;
    const float* Ab = A + ((size_t)b << 20);
    const float* V  = g_v + (size_t)b * SEQ * DQK;

    __shared__ __align__(16) float sA[16][128];   // [k][m]
    __shared__ __align__(16) float sV[16][192];   // [k][n]

    const int tid = threadIdx.x;
    const int row = tid & 127;
    const int kq  = tid >> 7;
    const int am  = (tid >> 4) << 2;
    const int tn4 = (tid & 15) << 2;

    unsigned long long acc[8][6];
#pragma unroll
    for (int i = 0; i < 8; i++)
#pragma unroll
        for (int j = 0; j < 6; j++) acc[i][j] = pack2(0.f, 0.f);

    float4 pa0, pa1, pv0, pv1, pv2;
    const size_t arow = (size_t)(m0 + row) * SEQ;
    // V load indices: f = r*256 + tid for r in 0..2 → nq = f%48, kk = f/48
    int vnq[3], vkk[3];
#pragma unroll
    for (int r = 0; r < 3; r++) {
        int f = r * 256 + tid;
        vnq[r] = f % 48; vkk[r] = f / 48;
    }

#define O_LOAD(kc) { int k0 = (kc) * 16; \
    pa0 = *reinterpret_cast<const float4*>(&Ab[arow + k0 + kq * 4]); \
    pa1 = *reinterpret_cast<const float4*>(&Ab[arow + k0 + (kq + 2) * 4]); \
    pv0 = *reinterpret_cast<const float4*>(&V[(size_t)(k0 + vkk[0]) * DQK + vnq[0] * 4]); \
    pv1 = *reinterpret_cast<const float4*>(&V[(size_t)(k0 + vkk[1]) * DQK + vnq[1] * 4]); \
    pv2 = *reinterpret_cast<const float4*>(&V[(size_t)(k0 + vkk[2]) * DQK + vnq[2] * 4]); }

#define O_STORE() { int c0 = kq * 4, c1 = (kq + 2) * 4; \
    sA[c0 + 0][row] = pa0.x; sA[c0 + 1][row] = pa0.y; sA[c0 + 2][row] = pa0.z; sA[c0 + 3][row] = pa0.w; \
    sA[c1 + 0][row] = pa1.x; sA[c1 + 1][row] = pa1.y; sA[c1 + 2][row] = pa1.z; sA[c1 + 3][row] = pa1.w; \
    reinterpret_cast<float4*>(&sV[vkk[0]][0])[vnq[0]] = pv0; \
    reinterpret_cast<float4*>(&sV[vkk[1]][0])[vnq[1]] = pv1; \
    reinterpret_cast<float4*>(&sV[vkk[2]][0])[vnq[2]] = pv2; }

    O_LOAD(0); O_STORE(); __syncthreads();

    for (int kc = 0; kc < 64; kc++) {
        if (kc < 63) O_LOAD(kc + 1);
#pragma unroll
        for (int kk = 0; kk < 16; kk++) {
            float4 a0 = *reinterpret_cast<const float4*>(&sA[kk][am]);
            float4 a1 = *reinterpret_cast<const float4*>(&sA[kk][64 + am]);
            const unsigned long long* br = reinterpret_cast<const unsigned long long*>(&sV[kk][0]);
            unsigned long long b0 = br[tn4 >> 1],         b1 = br[(tn4 >> 1) + 1];
            unsigned long long b2 = br[(64 + tn4) >> 1],  b3 = br[((64 + tn4) >> 1) + 1];
            unsigned long long b4 = br[(128 + tn4) >> 1], b5 = br[((128 + tn4) >> 1) + 1];
            float av[8] = {a0.x, a0.y, a0.z, a0.w, a1.x, a1.y, a1.z, a1.w};
#pragma unroll
            for (int i = 0; i < 8; i++) {
                unsigned long long ap = pack2(av[i], av[i]);
                ffma2(acc[i][0], ap, b0);
                ffma2(acc[i][1], ap, b1);
                ffma2(acc[i][2], ap, b2);
                ffma2(acc[i][3], ap, b3);
                ffma2(acc[i][4], ap, b4);
                ffma2(acc[i][5], ap, b5);
            }
        }
        __syncthreads();
        if (kc < 63) { O_STORE(); __syncthreads(); }
    }

    float* Ob = O + (size_t)b * SEQ * DQK;
#pragma unroll
    for (int i = 0; i < 8; i++) {
        int mi = m0 + ((i < 4) ? (am + i) : (64 + am + i - 4));
        float* rowp = Ob + (size_t)mi * DQK;
#pragma unroll
        for (int g = 0; g < 3; g++) {
            float2 plo = unpack2(acc[i][2 * g]), phi = unpack2(acc[i][2 * g + 1]);
            *reinterpret_cast<float4*>(&rowp[g * 64 + tn4]) = make_float4(plo.x, plo.y, phi.x, phi.y);
        }
    }
}

// ---------------- Kernel C4: in-place LayerNorm over 192 ----------------
__global__ void __launch_bounds__(192) ln_kernel(float* __restrict__ O,
                                                 const float* __restrict__ gamma,
                                                 const float* __restrict__ beta) {
    const int row = blockIdx.x;
    const int t = threadIdx.x;
    float* p = O + (size_t)row * DQK;
    float v = p[t];
    float s = v, s2 = v * v;
#pragma unroll
    for (int o = 16; o; o >>= 1) {
        s  += __shfl_xor_sync(0xffffffffu, s, o);
        s2 += __shfl_xor_sync(0xffffffffu, s2, o);
    }
    __shared__ float ws[6], ws2[6];
    __shared__ float mb[2];
    if ((t & 31) == 0) { ws[t >> 5] = s; ws2[t >> 5] = s2; }
    __syncthreads();
    if (t == 0) {
        float a = 0.f, b2 = 0.f;
#pragma unroll
        for (int i = 0; i < 6; i++) { a += ws[i]; b2 += ws2[i]; }
        float mean = a * (1.f / 192.f);
        float var  = b2 * (1.f / 192.f) - mean * mean;
        mb[0] = mean;
        mb[1] = rsqrtf(var + 1e-5f);
    }
    __syncthreads();
    p[t] = (v - mb[0]) * mb[1] * gamma[t] + beta[t];
}

// ---------------- launch ----------------
extern "C" void kernel_launch(void* const* d_in, const int* in_sizes, int n_in,
                              void* d_out, int out_size) {
    const float* x     = (const float*)d_in[0];
    const float* w     = (const float*)d_in[1];
    const float* ew    = (const float*)d_in[2];
    const float* tw    = (const float*)d_in[3];
    const float* gamma = (const float*)d_in[4];
    const float* beta  = (const float*)d_in[5];
    (void)in_sizes; (void)n_in; (void)out_size;

    float* out      = (float*)d_out;
    float* out_o    = out;                                  // [16,1024,192]
    float* out_attn = out + (size_t)NTOK * DQK;             // [16,1024,1024]

    build_U_kernel<<<48, 16>>>(w, ew, tw);
    qkv_kernel<<<dim3(16, NTOK / 128), 128>>>(x);
    scores_kernel<<<dim3(8, 8, 16), 256>>>(out_attn);
    softmax_kernel<<<NTOK, 256>>>(out_attn);
    o_kernel<<<dim3(1, 8, 16), 256>>>(out_attn, out_o);
    ln_kernel<<<NTOK, 192>>>(out_o, gamma, beta);
}